// round 9
// baseline (speedup 1.0000x reference)
#include <cuda_runtime.h>
#include <cuda_bf16.h>

#define CCONST 7.1998226
#define RPB 8          // rows per tile
#define THREADS 256
#define MAXB 64

__device__ double g_sum[MAXB];           // zero at load; reset by finalize each run
__device__ unsigned int g_tile = 0;      // work-stealing ticket; reset by finalize
__device__ unsigned int g_done = 0;      // completion ticket (atomicInc wraps)

// Block-wide fp64 reduce + atomic flush into g_sum[b]. Uniform control flow only.
__device__ __forceinline__ void block_flush(double acc, int b, double* sm, int tid) {
    #pragma unroll
    for (int off = 16; off; off >>= 1)
        acc += __shfl_down_sync(0xffffffffu, acc, off);
    if ((tid & 31) == 0) sm[tid >> 5] = acc;
    __syncthreads();
    if (tid < 32) {
        double w = (tid < THREADS / 32) ? sm[tid] : 0.0;
        #pragma unroll
        for (int off = 4; off; off >>= 1)
            w += __shfl_down_sync(0xffffffffu, w, off);
        if (tid == 0) atomicAdd(&g_sum[b], w);
    }
    __syncthreads();   // sm safe for reuse
}

template <int NC>
__global__ __launch_bounds__(THREADS, 4)
void coulomb_steal(const float* __restrict__ dij,
                   const float* __restrict__ q,
                   float* __restrict__ out,
                   int Nrt, int B, unsigned int nTiles, unsigned int totalBlocks) {
    const int N   = (NC > 0) ? NC : Nrt;
    const int tid = threadIdx.x;
    const int Tb  = N / RPB;
    const int j0  = tid * 8;

    __shared__ unsigned int s_next;
    __shared__ double sm[THREADS / 32];
    __shared__ bool is_last;

    // first claim
    if (tid == 0) s_next = atomicAdd(&g_tile, 1u);
    __syncthreads();
    unsigned int t = s_next;

    double acc = 0.0;
    int cur_b = -1;
    float4 qa = make_float4(0.f, 0.f, 0.f, 0.f);
    float4 qc = make_float4(0.f, 0.f, 0.f, 0.f);

    while (t < nTiles) {
        // BARRIER before overwrite: every thread has consumed the previous s_next
        __syncthreads();
        // prefetch next ticket; ATOMG latency hidden under this tile's compute
        if (tid == 0) s_next = atomicAdd(&g_tile, 1u);

        const int b  = (int)(t / (unsigned)Tb);
        const int rg = (int)(t - (unsigned)b * (unsigned)Tb);
        const float* qb = q + (size_t)b * N;

        if (b != cur_b) {                       // uniform: t uniform across block
            if (cur_b >= 0) { block_flush(acc, cur_b, sm, tid); acc = 0.0; }
            cur_b = b;
            qa = __ldg((const float4*)(qb + j0));
            qc = __ldg((const float4*)(qb + j0 + 4));
        }

        const int row0 = rg * RPB;
        const float* base = dij + ((size_t)b * N + row0) * (size_t)N + j0;

        float qi[RPB];
#pragma unroll
        for (int r = 0; r < RPB; r++) qi[r] = __ldg(qb + row0 + r);

        float acc0 = 0.0f, acc1 = 0.0f;

#pragma unroll
        for (int h = 0; h < RPB; h += 4) {
            float4 da0 = __ldcs((const float4*)(base + (size_t)(h + 0) * N));
            float4 dc0 = __ldcs((const float4*)(base + (size_t)(h + 0) * N) + 1);
            float4 da1 = __ldcs((const float4*)(base + (size_t)(h + 1) * N));
            float4 dc1 = __ldcs((const float4*)(base + (size_t)(h + 1) * N) + 1);
            float4 da2 = __ldcs((const float4*)(base + (size_t)(h + 2) * N));
            float4 dc2 = __ldcs((const float4*)(base + (size_t)(h + 2) * N) + 1);
            float4 da3 = __ldcs((const float4*)(base + (size_t)(h + 3) * N));
            float4 dc3 = __ldcs((const float4*)(base + (size_t)(h + 3) * N) + 1);

            float l0 = __fdividef(qa.x, da0.x) + __fdividef(qa.y, da0.y)
                     + __fdividef(qa.z, da0.z) + __fdividef(qa.w, da0.w)
                     + __fdividef(qc.x, dc0.x) + __fdividef(qc.y, dc0.y)
                     + __fdividef(qc.z, dc0.z) + __fdividef(qc.w, dc0.w);
            acc0 = fmaf(qi[h + 0], l0, acc0);

            float l1 = __fdividef(qa.x, da1.x) + __fdividef(qa.y, da1.y)
                     + __fdividef(qa.z, da1.z) + __fdividef(qa.w, da1.w)
                     + __fdividef(qc.x, dc1.x) + __fdividef(qc.y, dc1.y)
                     + __fdividef(qc.z, dc1.z) + __fdividef(qc.w, dc1.w);
            acc1 = fmaf(qi[h + 1], l1, acc1);

            float l2 = __fdividef(qa.x, da2.x) + __fdividef(qa.y, da2.y)
                     + __fdividef(qa.z, da2.z) + __fdividef(qa.w, da2.w)
                     + __fdividef(qc.x, dc2.x) + __fdividef(qc.y, dc2.y)
                     + __fdividef(qc.z, dc2.z) + __fdividef(qc.w, dc2.w);
            acc0 = fmaf(qi[h + 2], l2, acc0);

            float l3 = __fdividef(qa.x, da3.x) + __fdividef(qa.y, da3.y)
                     + __fdividef(qa.z, da3.z) + __fdividef(qa.w, da3.w)
                     + __fdividef(qc.x, dc3.x) + __fdividef(qc.y, dc3.y)
                     + __fdividef(qc.z, dc3.z) + __fdividef(qc.w, dc3.w);
            acc1 = fmaf(qi[h + 3], l3, acc1);
        }

        acc += (double)acc0 + (double)acc1;     // promote once per tile

        // BARRIER after compute: s_next (written above) is now published to all
        __syncthreads();
        t = s_next;
    }

    // final flush
    if (cur_b >= 0) block_flush(acc, cur_b, sm, tid);

    // completion ticket
    if (tid == 0) {
        __threadfence();
        unsigned int ticket = atomicInc(&g_done, totalBlocks - 1);
        is_last = (ticket == totalBlocks - 1);
    }
    __syncthreads();

    if (is_last) {
        if (tid == 0) g_tile = 0;               // reset ticket for next replay
        if (tid < B) {
            double total = atomicAdd(&g_sum[tid], 0.0);   // coherent read
            out[tid] = (float)(CCONST * total);
            g_sum[tid] = 0.0;                   // reset for next replay
        }
    }
}

extern "C" void kernel_launch(void* const* d_in, const int* in_sizes, int n_in,
                              void* d_out, int out_size) {
    // Identify inputs by element count: largest = d_ij [B,N,N]; q = [B,N].
    int di = 0;
    for (int i = 1; i < n_in; i++)
        if (in_sizes[i] > in_sizes[di]) di = i;
    const float* dij = (const float*)d_in[di];

    const long long B = (out_size > 0) ? out_size : 16;
    int qi = (di == 0 && n_in > 1) ? 1 : 0;
    for (int i = 0; i < n_in; i++) {
        if (i == di) continue;
        long long nq = in_sizes[i];
        long long Nc = nq / B;
        if (Nc > 0 && B * Nc * Nc == (long long)in_sizes[di]) { qi = i; break; }
    }
    const float* q = (const float*)d_in[qi];

    const int N = (int)((long long)in_sizes[qi] / B);   // 2048

    int sm_count = 148;
    cudaDeviceGetAttribute(&sm_count, cudaDevAttrMultiProcessorCount, 0);

    const unsigned int nTiles = (unsigned int)(B * (N / RPB));   // 4096
    unsigned int blocks = (unsigned int)(sm_count * 4);          // 4 CTAs/SM exactly
    if (blocks > nTiles) blocks = nTiles;

    if (N == 2048)
        coulomb_steal<2048><<<blocks, THREADS>>>(dij, q, (float*)d_out, N, (int)B, nTiles, blocks);
    else
        coulomb_steal<0><<<blocks, THREADS>>>(dij, q, (float*)d_out, N, (int)B, nTiles, blocks);
}